// round 2
// baseline (speedup 1.0000x reference)
#include <cuda_runtime.h>
#include <math.h>

#define N_NODESC 100000
#define N_EDGESC 3200000
#define E_TOT    (N_EDGESC + N_NODESC)
#define IN_DIMC  128
#define H1C      8
#define D1C      64     // H1*F1
#define NCC      40
#define NEG      0.2f

// ---------------- device scratch (no allocation allowed) ----------------
__device__ float    g_h1 [N_NODESC * D1C];
__device__ float    g_e1s[N_NODESC * H1C];
__device__ float    g_e1d[N_NODESC * H1C];
__device__ unsigned g_m1 [N_NODESC * H1C];
__device__ float    g_s1 [N_NODESC * H1C];
__device__ float    g_o1 [N_NODESC * D1C];
__device__ float    g_h2 [N_NODESC * NCC];
__device__ float    g_e2s[N_NODESC];
__device__ float    g_e2d[N_NODESC];
__device__ unsigned g_m2 [N_NODESC];
__device__ float    g_s2 [N_NODESC];
__device__ float    g_o2 [N_NODESC * NCC];
__device__ int      g_src[N_EDGESC];
__device__ int      g_dst[N_EDGESC];
__device__ int      g_is64;

// ordered-uint encoding for float atomicMax (monotone bijection)
__device__ __forceinline__ unsigned fenc(float f) {
    unsigned u = __float_as_uint(f);
    return (u & 0x80000000u) ? ~u : (u | 0x80000000u);
}
__device__ __forceinline__ float fdec(unsigned u) {
    return (u & 0x80000000u) ? __uint_as_float(u & 0x7fffffffu)
                             : __uint_as_float(~u);
}

// vectorized global reduction (sm_90+): 4 adds in one L2 transaction
__device__ __forceinline__ void red4(float* p, float a, float b, float c, float d) {
    asm volatile("red.global.add.v4.f32 [%0], {%1,%2,%3,%4};"
                 :: "l"(p), "f"(a), "f"(b), "f"(c), "f"(d) : "memory");
}

__device__ __forceinline__ float lrelu(float v) { return v > 0.f ? v : NEG * v; }

// ------- adjacency dtype probe: int64 iff first 256 int64s are valid ----
// (if the buffer is really int32, each int64 = lo + hi*2^32 with hi a random
//  node id; 256 consecutive zero-hi words has probability ~1e-1280)
__global__ void k_detect(const long long* __restrict__ adj) {
    if (threadIdx.x == 0) {
        int ok = 1;
        for (int i = 0; i < 256; i++) {
            long long v = adj[i];
            if (v < 0 || v >= N_NODESC) { ok = 0; break; }
        }
        g_is64 = ok;
    }
}

__global__ void k_convert(const void* __restrict__ adj) {
    int i = blockIdx.x * blockDim.x + threadIdx.x;
    if (i >= N_EDGESC) return;
    if (g_is64) {
        const long long* a = (const long long*)adj;
        g_src[i] = (int)a[i];
        g_dst[i] = (int)a[N_EDGESC + i];
    } else {
        const int* a = (const int*)adj;
        g_src[i] = a[i];
        g_dst[i] = a[N_EDGESC + i];
    }
}

__device__ __forceinline__ void edge_ids(int i, int& s, int& d) {
    if (i < N_EDGESC) { s = g_src[i]; d = g_dst[i]; }
    else              { s = d = i - N_EDGESC; }      // self loops
}

// ---------------- init: zero accumulators, reset maxes ----------------
__global__ void k_init() {
    int i = blockIdx.x * blockDim.x + threadIdx.x;           // 6.4M threads
    g_o1[i] = 0.f;
    if (i < N_NODESC * NCC) g_o2[i] = 0.f;
    if (i < N_NODESC * H1C) { g_s1[i] = 0.f; g_m1[i] = 0u; }
    if (i < N_NODESC)       { g_s2[i] = 0.f; g_m2[i] = 0u; }
}

// ---------------- GEMM1: h1 = x @ W1  (100000x128 @ 128x64) ------------
// block = 128 threads, handles 32 nodes x 64 cols; thread = 4 nodes x 4 cols
__global__ __launch_bounds__(128) void k_gemm1(const float* __restrict__ x,
                                               const float* __restrict__ W1) {
    __shared__ float xs[IN_DIMC][32];   // transposed: xs[k][node]  16KB
    __shared__ float ws[IN_DIMC][D1C];  //                          32KB
    const int t = threadIdx.x;
    const int base = blockIdx.x * 32;

    const float4* w4 = (const float4*)W1;           // 2048 float4
    for (int i = t; i < 2048; i += 128) {
        float4 v = w4[i];
        int k = i >> 4, j = (i & 15) << 2;
        ws[k][j] = v.x; ws[k][j+1] = v.y; ws[k][j+2] = v.z; ws[k][j+3] = v.w;
    }
    const float4* x4 = (const float4*)x;
    for (int i = t; i < 1024; i += 128) {           // 32 nodes * 32 float4
        int node = i >> 5, kq = i & 31;
        float4 v = x4[(base + node) * 32 + kq];
        int k = kq * 4;
        xs[k][node] = v.x; xs[k+1][node] = v.y; xs[k+2][node] = v.z; xs[k+3][node] = v.w;
    }
    __syncthreads();

    const int cg = t & 15;   // 16 col-groups of 4
    const int ng = t >> 4;   // 8 node-groups of 4
    float acc[4][4];
    #pragma unroll
    for (int i = 0; i < 4; i++)
        #pragma unroll
        for (int j = 0; j < 4; j++) acc[i][j] = 0.f;

    #pragma unroll 8
    for (int k = 0; k < IN_DIMC; k++) {
        float4 xv = *(const float4*)&xs[k][ng * 4];
        float4 wv = *(const float4*)&ws[k][cg * 4];
        acc[0][0] += xv.x*wv.x; acc[0][1] += xv.x*wv.y; acc[0][2] += xv.x*wv.z; acc[0][3] += xv.x*wv.w;
        acc[1][0] += xv.y*wv.x; acc[1][1] += xv.y*wv.y; acc[1][2] += xv.y*wv.z; acc[1][3] += xv.y*wv.w;
        acc[2][0] += xv.z*wv.x; acc[2][1] += xv.z*wv.y; acc[2][2] += xv.z*wv.z; acc[2][3] += xv.z*wv.w;
        acc[3][0] += xv.w*wv.x; acc[3][1] += xv.w*wv.y; acc[3][2] += xv.w*wv.z; acc[3][3] += xv.w*wv.w;
    }
    #pragma unroll
    for (int i = 0; i < 4; i++) {
        float4 o = make_float4(acc[i][0], acc[i][1], acc[i][2], acc[i][3]);
        *(float4*)&g_h1[(base + ng * 4 + i) * D1C + cg * 4] = o;
    }
}

// -------- per-node attention logits layer1: e1s/e1d[n,h] (warp/node) ----
__global__ void k_nodeE1(const float* __restrict__ a1s, const float* __restrict__ a1d) {
    int warp = (blockIdx.x * blockDim.x + threadIdx.x) >> 5;
    int lane = threadIdx.x & 31;
    if (warp >= N_NODESC) return;
    float v1 = g_h1[warp * D1C + lane];
    float v2 = g_h1[warp * D1C + 32 + lane];
    float s1v = v1 * a1s[lane],      s2v = v2 * a1s[32 + lane];
    float d1v = v1 * a1d[lane],      d2v = v2 * a1d[32 + lane];
    #pragma unroll
    for (int o = 4; o; o >>= 1) {
        s1v += __shfl_down_sync(0xffffffffu, s1v, o);
        s2v += __shfl_down_sync(0xffffffffu, s2v, o);
        d1v += __shfl_down_sync(0xffffffffu, d1v, o);
        d2v += __shfl_down_sync(0xffffffffu, d2v, o);
    }
    if ((lane & 7) == 0) {
        int h = lane >> 3;
        g_e1s[warp * H1C + h]     = s1v;
        g_e1s[warp * H1C + 4 + h] = s2v;
        g_e1d[warp * H1C + h]     = d1v;
        g_e1d[warp * H1C + 4 + h] = d2v;
    }
}

// ---------------- edge pass A1: segment max -----------------------------
__global__ void k_emax1() {
    int i = blockIdx.x * blockDim.x + threadIdx.x;
    if (i >= E_TOT) return;
    int s, d; edge_ids(i, s, d);
    float4 a0 = *(const float4*)&g_e1s[s * H1C];
    float4 a1 = *(const float4*)&g_e1s[s * H1C + 4];
    float4 b0 = *(const float4*)&g_e1d[d * H1C];
    float4 b1 = *(const float4*)&g_e1d[d * H1C + 4];
    float e[8] = {a0.x+b0.x, a0.y+b0.y, a0.z+b0.z, a0.w+b0.w,
                  a1.x+b1.x, a1.y+b1.y, a1.z+b1.z, a1.w+b1.w};
    #pragma unroll
    for (int h = 0; h < H1C; h++)
        atomicMax(&g_m1[d * H1C + h], fenc(lrelu(e[h])));
}

// ---------------- edge pass B1: exp-sum + weighted feature scatter ------
__global__ void k_eagg1() {
    int i = blockIdx.x * blockDim.x + threadIdx.x;
    if (i >= E_TOT) return;
    int s, d; edge_ids(i, s, d);
    float4 a0 = *(const float4*)&g_e1s[s * H1C];
    float4 a1 = *(const float4*)&g_e1s[s * H1C + 4];
    float4 b0 = *(const float4*)&g_e1d[d * H1C];
    float4 b1 = *(const float4*)&g_e1d[d * H1C + 4];
    uint4 m0 = *(const uint4*)&g_m1[d * H1C];
    uint4 m1 = *(const uint4*)&g_m1[d * H1C + 4];
    float p[8];
    p[0] = __expf(lrelu(a0.x+b0.x) - fdec(m0.x));
    p[1] = __expf(lrelu(a0.y+b0.y) - fdec(m0.y));
    p[2] = __expf(lrelu(a0.z+b0.z) - fdec(m0.z));
    p[3] = __expf(lrelu(a0.w+b0.w) - fdec(m0.w));
    p[4] = __expf(lrelu(a1.x+b1.x) - fdec(m1.x));
    p[5] = __expf(lrelu(a1.y+b1.y) - fdec(m1.y));
    p[6] = __expf(lrelu(a1.z+b1.z) - fdec(m1.z));
    p[7] = __expf(lrelu(a1.w+b1.w) - fdec(m1.w));
    red4(&g_s1[d * H1C],     p[0], p[1], p[2], p[3]);
    red4(&g_s1[d * H1C + 4], p[4], p[5], p[6], p[7]);
    #pragma unroll
    for (int h = 0; h < H1C; h++) {
        float4 hv0 = *(const float4*)&g_h1[s * D1C + h * 8];
        float4 hv1 = *(const float4*)&g_h1[s * D1C + h * 8 + 4];
        float ph = p[h];
        red4(&g_o1[d * D1C + h * 8],     ph*hv0.x, ph*hv0.y, ph*hv0.z, ph*hv0.w);
        red4(&g_o1[d * D1C + h * 8 + 4], ph*hv1.x, ph*hv1.y, ph*hv1.z, ph*hv1.w);
    }
}

// -------- GEMM2 fused with layer1 finalize (divide + ELU) ---------------
// block = 320 threads = 8 nodes x 40 classes
__global__ __launch_bounds__(320) void k_gemm2(const float* __restrict__ W2) {
    __shared__ float xs[8][D1C];
    __shared__ float ws[D1C][NCC];
    const int t = threadIdx.x;
    const int base = blockIdx.x * 8;
    for (int i = t; i < D1C * NCC; i += 320) ws[i / NCC][i % NCC] = W2[i];
    for (int i = t; i < 8 * D1C; i += 320) {
        int n = i >> 6, j = i & 63;
        float v = g_o1[(base + n) * D1C + j] / g_s1[(base + n) * H1C + (j >> 3)];
        xs[n][j] = v > 0.f ? v : (__expf(v) - 1.f);     // ELU
    }
    __syncthreads();
    const int n = t / NCC, c = t % NCC;
    float acc = 0.f;
    #pragma unroll 8
    for (int k = 0; k < D1C; k++) acc += xs[n][k] * ws[k][c];
    g_h2[(base + n) * NCC + c] = acc;
}

// -------- per-node logits layer2 (1 head, 40 feats): warp/node ----------
__global__ void k_nodeE2(const float* __restrict__ a2s, const float* __restrict__ a2d) {
    int warp = (blockIdx.x * blockDim.x + threadIdx.x) >> 5;
    int lane = threadIdx.x & 31;
    if (warp >= N_NODESC) return;
    float v1 = g_h2[warp * NCC + lane];
    float sv = v1 * a2s[lane];
    float dv = v1 * a2d[lane];
    if (lane < 8) {
        float v2 = g_h2[warp * NCC + 32 + lane];
        sv += v2 * a2s[32 + lane];
        dv += v2 * a2d[32 + lane];
    }
    #pragma unroll
    for (int o = 16; o; o >>= 1) {
        sv += __shfl_down_sync(0xffffffffu, sv, o);
        dv += __shfl_down_sync(0xffffffffu, dv, o);
    }
    if (lane == 0) { g_e2s[warp] = sv; g_e2d[warp] = dv; }
}

__global__ void k_emax2() {
    int i = blockIdx.x * blockDim.x + threadIdx.x;
    if (i >= E_TOT) return;
    int s, d; edge_ids(i, s, d);
    atomicMax(&g_m2[d], fenc(lrelu(g_e2s[s] + g_e2d[d])));
}

__global__ void k_eagg2() {
    int i = blockIdx.x * blockDim.x + threadIdx.x;
    if (i >= E_TOT) return;
    int s, d; edge_ids(i, s, d);
    float p = __expf(lrelu(g_e2s[s] + g_e2d[d]) - fdec(g_m2[d]));
    atomicAdd(&g_s2[d], p);
    #pragma unroll
    for (int q = 0; q < NCC / 4; q++) {
        float4 hv = *(const float4*)&g_h2[s * NCC + q * 4];
        red4(&g_o2[d * NCC + q * 4], p*hv.x, p*hv.y, p*hv.z, p*hv.w);
    }
}

// -------- finalize: normalize + log_softmax, warp per node --------------
__global__ void k_final(float* __restrict__ out) {
    int n = (blockIdx.x * blockDim.x + threadIdx.x) >> 5;
    int lane = threadIdx.x & 31;
    if (n >= N_NODESC) return;
    float inv = 1.f / g_s2[n];
    float l1 = g_o2[n * NCC + lane] * inv;
    float l2 = (lane < 8) ? g_o2[n * NCC + 32 + lane] * inv : -1e30f;
    float m = fmaxf(l1, l2);
    #pragma unroll
    for (int o = 16; o; o >>= 1) m = fmaxf(m, __shfl_xor_sync(0xffffffffu, m, o));
    float se = __expf(l1 - m) + ((lane < 8) ? __expf(l2 - m) : 0.f);
    #pragma unroll
    for (int o = 16; o; o >>= 1) se += __shfl_xor_sync(0xffffffffu, se, o);
    float lse = m + logf(se);
    out[n * NCC + lane] = l1 - lse;
    if (lane < 8) out[n * NCC + 32 + lane] = l2 - lse;
}

// ------------------------------------------------------------------------
extern "C" void kernel_launch(void* const* d_in, const int* in_sizes, int n_in,
                              void* d_out, int out_size) {
    const float* x   = (const float*)d_in[0];
    const void*  adj = d_in[1];
    const float* W1  = (const float*)d_in[2];
    const float* a1s = (const float*)d_in[3];
    const float* a1d = (const float*)d_in[4];
    const float* W2  = (const float*)d_in[5];
    const float* a2s = (const float*)d_in[6];
    const float* a2d = (const float*)d_in[7];
    float* out = (float*)d_out;

    const int eg = (E_TOT + 255) / 256;

    k_detect <<<1, 32>>>((const long long*)adj);
    k_convert<<<(N_EDGESC + 255) / 256, 256>>>(adj);
    k_init   <<<(N_NODESC * D1C) / 256, 256>>>();
    k_gemm1  <<<N_NODESC / 32, 128>>>(x, W1);
    k_nodeE1 <<<N_NODESC / 8, 256>>>(a1s, a1d);
    k_emax1  <<<eg, 256>>>();
    k_eagg1  <<<eg, 256>>>();
    k_gemm2  <<<N_NODESC / 8, 320>>>(W2);
    k_nodeE2 <<<N_NODESC / 8, 256>>>(a2s, a2d);
    k_emax2  <<<eg, 256>>>();
    k_eagg2  <<<eg, 256>>>();
    k_final  <<<N_NODESC / 8, 256>>>(out);
}

// round 3
// speedup vs baseline: 2.2985x; 2.2985x over previous
#include <cuda_runtime.h>
#include <math.h>

#define N_NODESC 100000
#define N_EDGESC 3200000
#define IN_DIMC  128
#define H1C      8
#define D1C      64     // H1*F1
#define NCC      40
#define NEG      0.2f
#define NB_SCAN  196    // ceil(100000/512)

// ---------------- device scratch (no allocation allowed) ----------------
__device__ float    g_h1 [N_NODESC * D1C];
__device__ float    g_e1s[N_NODESC * H1C];
__device__ float    g_e1d[N_NODESC * H1C];
__device__ float    g_x2 [N_NODESC * D1C];
__device__ float    g_h2 [N_NODESC * NCC];
__device__ float    g_e2s[N_NODESC];
__device__ float    g_e2d[N_NODESC];
__device__ int      g_deg [N_NODESC];
__device__ int      g_cur [N_NODESC];
__device__ int      g_off [N_NODESC];
__device__ int      g_scan[N_NODESC];
__device__ int      g_bsum[NB_SCAN];
__device__ int      g_boff[NB_SCAN];
__device__ int      g_csr [N_EDGESC];
__device__ int      g_is64;

__device__ __forceinline__ float lrelu(float v) { return v > 0.f ? v : NEG * v; }

// ------- adjacency dtype probe: int64 iff first 256 int64s are valid ----
__global__ void k_detect(const long long* __restrict__ adj) {
    if (threadIdx.x == 0) {
        int ok = 1;
        for (int i = 0; i < 256; i++) {
            long long v = adj[i];
            if (v < 0 || v >= N_NODESC) { ok = 0; break; }
        }
        g_is64 = ok;
    }
}

__device__ __forceinline__ int load_idx(const void* adj, long long pos) {
    return g_is64 ? (int)((const long long*)adj)[pos] : ((const int*)adj)[pos];
}

// ---------------- init: zero degree + cursor ----------------------------
__global__ void k_init() {
    int i = blockIdx.x * blockDim.x + threadIdx.x;
    if (i < N_NODESC) { g_deg[i] = 0; g_cur[i] = 0; }
}

// ---------------- CSR build: histogram, scan, fill ----------------------
__global__ void k_hist(const void* __restrict__ adj) {
    int i = blockIdx.x * blockDim.x + threadIdx.x;
    if (i >= N_EDGESC) return;
    int d = load_idx(adj, (long long)N_EDGESC + i);
    atomicAdd(&g_deg[d], 1);
}

__global__ __launch_bounds__(512) void k_scan1() {
    __shared__ int sh[512];
    int t = threadIdx.x;
    int i = blockIdx.x * 512 + t;
    int v = (i < N_NODESC) ? g_deg[i] : 0;
    sh[t] = v;
    __syncthreads();
    #pragma unroll
    for (int off = 1; off < 512; off <<= 1) {
        int add = (t >= off) ? sh[t - off] : 0;
        __syncthreads();
        sh[t] += add;
        __syncthreads();
    }
    if (i < N_NODESC) g_scan[i] = sh[t];
    if (t == 511) g_bsum[blockIdx.x] = sh[511];
}

__global__ __launch_bounds__(256) void k_scan2() {
    __shared__ int sh[256];
    int t = threadIdx.x;
    sh[t] = (t < NB_SCAN) ? g_bsum[t] : 0;
    __syncthreads();
    #pragma unroll
    for (int off = 1; off < 256; off <<= 1) {
        int add = (t >= off) ? sh[t - off] : 0;
        __syncthreads();
        sh[t] += add;
        __syncthreads();
    }
    if (t < NB_SCAN) g_boff[t] = sh[t];
}

__global__ void k_scan3() {
    int i = blockIdx.x * blockDim.x + threadIdx.x;
    if (i >= N_NODESC) return;
    int b = i >> 9;
    int base = (b > 0) ? g_boff[b - 1] : 0;
    g_off[i] = g_scan[i] - g_deg[i] + base;     // exclusive global offset
}

__global__ void k_fill(const void* __restrict__ adj) {
    int i = blockIdx.x * blockDim.x + threadIdx.x;
    if (i >= N_EDGESC) return;
    int s = load_idx(adj, i);
    int d = load_idx(adj, (long long)N_EDGESC + i);
    int pos = atomicAdd(&g_cur[d], 1);
    g_csr[g_off[d] + pos] = s;
}

// ---------------- GEMM1: h1 = x @ W1  (100000x128 @ 128x64) -------------
// 128 threads, tile 128 nodes x 64 cols, 8x8 per thread, k-chunks of 32
__global__ __launch_bounds__(128) void k_gemm1(const float* __restrict__ x,
                                               const float* __restrict__ W1) {
    __shared__ float xs[32][132];   // [k][node], padded
    __shared__ float ws[32][64];    // [k][col]
    const int t = threadIdx.x;
    const int base = blockIdx.x * 128;
    const int ng = t >> 3;          // 0..15, 8 nodes each
    const int cg = t & 7;           // 0..7,  8 cols each

    float acc[8][8];
    #pragma unroll
    for (int i = 0; i < 8; i++)
        #pragma unroll
        for (int j = 0; j < 8; j++) acc[i][j] = 0.f;

    for (int kc = 0; kc < IN_DIMC; kc += 32) {
        // W chunk: 32x64 = 512 float4
        for (int i = t; i < 512; i += 128) {
            int k = i >> 4, j = (i & 15) << 2;
            float4 v = *(const float4*)&W1[(kc + k) * D1C + j];
            ws[k][j] = v.x; ws[k][j+1] = v.y; ws[k][j+2] = v.z; ws[k][j+3] = v.w;
        }
        // X chunk transposed: 128 nodes x 32 k = 1024 float4
        for (int i = t; i < 1024; i += 128) {
            int node = i >> 3, kq = i & 7;
            int gn = base + node;
            float4 v = make_float4(0.f, 0.f, 0.f, 0.f);
            if (gn < N_NODESC) v = *(const float4*)&x[gn * IN_DIMC + kc + kq * 4];
            int k = kq * 4;
            xs[k][node] = v.x; xs[k+1][node] = v.y; xs[k+2][node] = v.z; xs[k+3][node] = v.w;
        }
        __syncthreads();
        #pragma unroll 8
        for (int k = 0; k < 32; k++) {
            float4 xa = *(const float4*)&xs[k][ng * 8];
            float4 xb = *(const float4*)&xs[k][ng * 8 + 4];
            float4 wa = *(const float4*)&ws[k][cg * 8];
            float4 wb = *(const float4*)&ws[k][cg * 8 + 4];
            float xv[8] = {xa.x, xa.y, xa.z, xa.w, xb.x, xb.y, xb.z, xb.w};
            float wv[8] = {wa.x, wa.y, wa.z, wa.w, wb.x, wb.y, wb.z, wb.w};
            #pragma unroll
            for (int i = 0; i < 8; i++)
                #pragma unroll
                for (int j = 0; j < 8; j++) acc[i][j] += xv[i] * wv[j];
        }
        __syncthreads();
    }
    #pragma unroll
    for (int i = 0; i < 8; i++) {
        int gn = base + ng * 8 + i;
        if (gn < N_NODESC) {
            *(float4*)&g_h1[gn * D1C + cg * 8]     = make_float4(acc[i][0], acc[i][1], acc[i][2], acc[i][3]);
            *(float4*)&g_h1[gn * D1C + cg * 8 + 4] = make_float4(acc[i][4], acc[i][5], acc[i][6], acc[i][7]);
        }
    }
}

// -------- per-node attention logits layer1: e1s/e1d[n,h] (warp/node) ----
__global__ void k_nodeE1(const float* __restrict__ a1s, const float* __restrict__ a1d) {
    int warp = (blockIdx.x * blockDim.x + threadIdx.x) >> 5;
    int lane = threadIdx.x & 31;
    if (warp >= N_NODESC) return;
    float v1 = g_h1[warp * D1C + lane];
    float v2 = g_h1[warp * D1C + 32 + lane];
    float s1v = v1 * a1s[lane],      s2v = v2 * a1s[32 + lane];
    float d1v = v1 * a1d[lane],      d2v = v2 * a1d[32 + lane];
    #pragma unroll
    for (int o = 4; o; o >>= 1) {
        s1v += __shfl_down_sync(0xffffffffu, s1v, o);
        s2v += __shfl_down_sync(0xffffffffu, s2v, o);
        d1v += __shfl_down_sync(0xffffffffu, d1v, o);
        d2v += __shfl_down_sync(0xffffffffu, d2v, o);
    }
    if ((lane & 7) == 0) {
        int h = lane >> 3;
        g_e1s[warp * H1C + h]     = s1v;
        g_e1s[warp * H1C + 4 + h] = s2v;
        g_e1d[warp * H1C + h]     = d1v;
        g_e1d[warp * H1C + 4 + h] = d2v;
    }
}

// -------- layer1 gather: warp per dst, fused softmax-norm + ELU ---------
// lane l accumulates feats l and 32+l (heads l>>3 and 4+(l>>3));
// lane's "own" head for p is (l & 7). No max subtraction (logits |e| < ~6).
__global__ void k_agg1() {
    int d    = (blockIdx.x * blockDim.x + threadIdx.x) >> 5;
    int lane = threadIdx.x & 31;
    if (d >= N_NODESC) return;
    const int h8 = lane & 7;
    const int la = lane >> 3, lb = 4 + (lane >> 3);
    float ed = g_e1d[d * H1C + h8];

    // self loop
    float p = __expf(lrelu(g_e1s[d * H1C + h8] + ed));
    float psum = p;
    float pa = __shfl_sync(0xffffffffu, p, la);
    float pb = __shfl_sync(0xffffffffu, p, lb);
    float acc0 = pa * g_h1[d * D1C + lane];
    float acc1 = pb * g_h1[d * D1C + 32 + lane];

    int beg = g_off[d], n = g_deg[d];
    int s = (n > 0) ? g_csr[beg] : 0;
    for (int j = 0; j < n; j++) {
        int s_next = (j + 1 < n) ? g_csr[beg + j + 1] : 0;
        float es = g_e1s[s * H1C + h8];
        p = __expf(lrelu(es + ed));
        psum += p;
        pa = __shfl_sync(0xffffffffu, p, la);
        pb = __shfl_sync(0xffffffffu, p, lb);
        acc0 += pa * g_h1[s * D1C + lane];
        acc1 += pb * g_h1[s * D1C + 32 + lane];
        s = s_next;
    }
    float sa = __shfl_sync(0xffffffffu, psum, la);
    float sb = __shfl_sync(0xffffffffu, psum, lb);
    float v0 = acc0 / sa, v1 = acc1 / sb;
    g_x2[d * D1C + lane]      = v0 > 0.f ? v0 : (__expf(v0) - 1.f);
    g_x2[d * D1C + 32 + lane] = v1 > 0.f ? v1 : (__expf(v1) - 1.f);
}

// -------- GEMM2: h2 = x2 @ W2 (100000x64 @ 64x40) -----------------------
__global__ __launch_bounds__(320) void k_gemm2(const float* __restrict__ W2) {
    __shared__ float xs[8][D1C];
    __shared__ float ws[D1C][NCC];
    const int t = threadIdx.x;
    const int base = blockIdx.x * 8;
    for (int i = t; i < D1C * NCC; i += 320) ws[i / NCC][i % NCC] = W2[i];
    for (int i = t; i < 8 * D1C; i += 320) {
        int n = i >> 6, j = i & 63;
        xs[n][j] = g_x2[(base + n) * D1C + j];
    }
    __syncthreads();
    const int n = t / NCC, c = t % NCC;
    float acc = 0.f;
    #pragma unroll 8
    for (int k = 0; k < D1C; k++) acc += xs[n][k] * ws[k][c];
    g_h2[(base + n) * NCC + c] = acc;
}

// -------- per-node logits layer2 (1 head, 40 feats): warp/node ----------
__global__ void k_nodeE2(const float* __restrict__ a2s, const float* __restrict__ a2d) {
    int warp = (blockIdx.x * blockDim.x + threadIdx.x) >> 5;
    int lane = threadIdx.x & 31;
    if (warp >= N_NODESC) return;
    float v1 = g_h2[warp * NCC + lane];
    float sv = v1 * a2s[lane];
    float dv = v1 * a2d[lane];
    if (lane < 8) {
        float v2 = g_h2[warp * NCC + 32 + lane];
        sv += v2 * a2s[32 + lane];
        dv += v2 * a2d[32 + lane];
    }
    #pragma unroll
    for (int o = 16; o; o >>= 1) {
        sv += __shfl_down_sync(0xffffffffu, sv, o);
        dv += __shfl_down_sync(0xffffffffu, dv, o);
    }
    if (lane == 0) { g_e2s[warp] = sv; g_e2d[warp] = dv; }
}

// -------- layer2 gather + log_softmax, warp per dst ---------------------
__global__ void k_agg2(float* __restrict__ out) {
    int d    = (blockIdx.x * blockDim.x + threadIdx.x) >> 5;
    int lane = threadIdx.x & 31;
    if (d >= N_NODESC) return;
    float ed = g_e2d[d];

    float p = __expf(lrelu(g_e2s[d] + ed));     // self loop
    float psum = p;
    float acc0 = p * g_h2[d * NCC + lane];
    float acc1 = (lane < 8) ? p * g_h2[d * NCC + 32 + lane] : 0.f;

    int beg = g_off[d], n = g_deg[d];
    int s = (n > 0) ? g_csr[beg] : 0;
    for (int j = 0; j < n; j++) {
        int s_next = (j + 1 < n) ? g_csr[beg + j + 1] : 0;
        p = __expf(lrelu(g_e2s[s] + ed));
        psum += p;
        acc0 += p * g_h2[s * NCC + lane];
        if (lane < 8) acc1 += p * g_h2[s * NCC + 32 + lane];
        s = s_next;
    }
    float inv = 1.f / psum;
    float l1 = acc0 * inv;
    float l2 = (lane < 8) ? acc1 * inv : -1e30f;
    float m = fmaxf(l1, l2);
    #pragma unroll
    for (int o = 16; o; o >>= 1) m = fmaxf(m, __shfl_xor_sync(0xffffffffu, m, o));
    float se = __expf(l1 - m) + ((lane < 8) ? __expf(l2 - m) : 0.f);
    #pragma unroll
    for (int o = 16; o; o >>= 1) se += __shfl_xor_sync(0xffffffffu, se, o);
    float lse = m + logf(se);
    out[d * NCC + lane] = l1 - lse;
    if (lane < 8) out[d * NCC + 32 + lane] = l2 - lse;
}

// ------------------------------------------------------------------------
extern "C" void kernel_launch(void* const* d_in, const int* in_sizes, int n_in,
                              void* d_out, int out_size) {
    const float* x   = (const float*)d_in[0];
    const void*  adj = d_in[1];
    const float* W1  = (const float*)d_in[2];
    const float* a1s = (const float*)d_in[3];
    const float* a1d = (const float*)d_in[4];
    const float* W2  = (const float*)d_in[5];
    const float* a2s = (const float*)d_in[6];
    const float* a2d = (const float*)d_in[7];
    float* out = (float*)d_out;

    const int eg = (N_EDGESC + 255) / 256;      // 12500
    const int ng = (N_NODESC + 255) / 256;      // 391
    const int wg = N_NODESC / 8;                // 12500 (warp per node)

    k_init   <<<ng, 256>>>();
    k_detect <<<1, 32>>>((const long long*)adj);
    k_hist   <<<eg, 256>>>(adj);
    k_scan1  <<<NB_SCAN, 512>>>();
    k_scan2  <<<1, 256>>>();
    k_scan3  <<<ng, 256>>>();
    k_fill   <<<eg, 256>>>(adj);
    k_gemm1  <<<(N_NODESC + 127) / 128, 128>>>(x, W1);
    k_nodeE1 <<<wg, 256>>>(a1s, a1d);
    k_agg1   <<<wg, 256>>>();
    k_gemm2  <<<(N_NODESC + 7) / 8, 320>>>(W2);
    k_nodeE2 <<<wg, 256>>>(a2s, a2d);
    k_agg2   <<<wg, 256>>>(out);
}

// round 5
// speedup vs baseline: 2.6202x; 1.1400x over previous
#include <cuda_runtime.h>
#include <math.h>

#define N_NODESC 100000
#define N_EDGESC 3200000
#define IN_DIMC  128
#define H1C      8
#define D1C      64     // H1*F1
#define NCC      40
#define NEG      0.2f
#define NB_SCAN  196    // ceil(100000/512)
#define FULLM    0xffffffffu

// ---------------- device scratch (no allocation allowed) ----------------
__device__ float    g_h1 [N_NODESC * D1C];
__device__ float    g_e1s[N_NODESC * H1C];
__device__ float    g_e1d[N_NODESC * H1C];
__device__ float    g_x2 [N_NODESC * D1C];
__device__ float    g_h2 [N_NODESC * NCC];
__device__ float    g_e2s[N_NODESC];
__device__ float    g_e2d[N_NODESC];
__device__ int      g_deg [N_NODESC];
__device__ int      g_cur [N_NODESC];
__device__ int      g_off [N_NODESC];
__device__ int      g_scan[N_NODESC];
__device__ int      g_bsum[NB_SCAN];
__device__ int      g_boff[NB_SCAN];
__device__ int      g_csr [N_EDGESC];
__device__ int      g_is64;

__device__ __forceinline__ float lrelu(float v) { return v > 0.f ? v : NEG * v; }

// ------- adjacency dtype probe: int64 iff first 256 int64s are valid ----
__global__ void k_detect(const long long* __restrict__ adj) {
    if (threadIdx.x == 0) {
        int ok = 1;
        for (int i = 0; i < 256; i++) {
            long long v = adj[i];
            if (v < 0 || v >= N_NODESC) { ok = 0; break; }
        }
        g_is64 = ok;
    }
}

__device__ __forceinline__ int load_idx(const void* adj, long long pos) {
    return g_is64 ? (int)((const long long*)adj)[pos] : ((const int*)adj)[pos];
}

// ---------------- init: zero degree ------------------------------------
__global__ void k_init() {
    int i = blockIdx.x * blockDim.x + threadIdx.x;
    if (i < N_NODESC) g_deg[i] = 0;
}

// ---------------- CSR build: histogram, scan, fill ----------------------
__global__ void k_hist(const void* __restrict__ adj) {
    int i = blockIdx.x * blockDim.x + threadIdx.x;
    if (i >= N_EDGESC) return;
    int d = load_idx(adj, (long long)N_EDGESC + i);
    atomicAdd(&g_deg[d], 1);
}

__global__ __launch_bounds__(512) void k_scan1() {
    __shared__ int sh[512];
    int t = threadIdx.x;
    int i = blockIdx.x * 512 + t;
    int v = (i < N_NODESC) ? g_deg[i] : 0;
    sh[t] = v;
    __syncthreads();
    #pragma unroll
    for (int off = 1; off < 512; off <<= 1) {
        int add = (t >= off) ? sh[t - off] : 0;
        __syncthreads();
        sh[t] += add;
        __syncthreads();
    }
    if (i < N_NODESC) g_scan[i] = sh[t];
    if (t == 511) g_bsum[blockIdx.x] = sh[511];
}

__global__ __launch_bounds__(256) void k_scan2() {
    __shared__ int sh[256];
    int t = threadIdx.x;
    sh[t] = (t < NB_SCAN) ? g_bsum[t] : 0;
    __syncthreads();
    #pragma unroll
    for (int off = 1; off < 256; off <<= 1) {
        int add = (t >= off) ? sh[t - off] : 0;
        __syncthreads();
        sh[t] += add;
        __syncthreads();
    }
    if (t < NB_SCAN) g_boff[t] = sh[t];
}

__global__ void k_scan3() {
    int i = blockIdx.x * blockDim.x + threadIdx.x;
    if (i >= N_NODESC) return;
    int b = i >> 9;
    int base = (b > 0) ? g_boff[b - 1] : 0;
    int start = g_scan[i] - g_deg[i] + base;    // exclusive global offset
    g_off[i] = start;
    g_cur[i] = start;                           // absolute running cursor
}

__global__ void k_fill(const void* __restrict__ adj) {
    int i = blockIdx.x * blockDim.x + threadIdx.x;
    if (i >= N_EDGESC) return;
    int s = load_idx(adj, i);
    int d = load_idx(adj, (long long)N_EDGESC + i);
    int pos = atomicAdd(&g_cur[d], 1);
    g_csr[pos] = s;
}

// ------- GEMM1 + fused e1s/e1d: h1 = x @ W1 (100000x128 @ 128x64) -------
// 128 threads, tile 128 nodes x 64 cols, 8x8 per thread, k-chunks of 32.
// Thread (ng,cg) holds full head cg for its 8 nodes -> e1s/e1d are local dots.
__global__ __launch_bounds__(128) void k_gemm1(const float* __restrict__ x,
                                               const float* __restrict__ W1,
                                               const float* __restrict__ a1s,
                                               const float* __restrict__ a1d) {
    __shared__ float xs[32][132];   // [k][node], padded
    __shared__ float ws[32][64];    // [k][col]
    const int t = threadIdx.x;
    const int base = blockIdx.x * 128;
    const int ng = t >> 3;          // 0..15, 8 nodes each
    const int cg = t & 7;           // 0..7 = head, 8 cols each

    float acc[8][8];
    #pragma unroll
    for (int i = 0; i < 8; i++)
        #pragma unroll
        for (int j = 0; j < 8; j++) acc[i][j] = 0.f;

    for (int kc = 0; kc < IN_DIMC; kc += 32) {
        for (int i = t; i < 512; i += 128) {
            int k = i >> 4, j = (i & 15) << 2;
            float4 v = *(const float4*)&W1[(kc + k) * D1C + j];
            ws[k][j] = v.x; ws[k][j+1] = v.y; ws[k][j+2] = v.z; ws[k][j+3] = v.w;
        }
        for (int i = t; i < 1024; i += 128) {
            int node = i >> 3, kq = i & 7;
            int gn = base + node;
            float4 v = make_float4(0.f, 0.f, 0.f, 0.f);
            if (gn < N_NODESC) v = *(const float4*)&x[gn * IN_DIMC + kc + kq * 4];
            int k = kq * 4;
            xs[k][node] = v.x; xs[k+1][node] = v.y; xs[k+2][node] = v.z; xs[k+3][node] = v.w;
        }
        __syncthreads();
        #pragma unroll 8
        for (int k = 0; k < 32; k++) {
            float4 xa = *(const float4*)&xs[k][ng * 8];
            float4 xb = *(const float4*)&xs[k][ng * 8 + 4];
            float4 wa = *(const float4*)&ws[k][cg * 8];
            float4 wb = *(const float4*)&ws[k][cg * 8 + 4];
            float xv[8] = {xa.x, xa.y, xa.z, xa.w, xb.x, xb.y, xb.z, xb.w};
            float wv[8] = {wa.x, wa.y, wa.z, wa.w, wb.x, wb.y, wb.z, wb.w};
            #pragma unroll
            for (int i = 0; i < 8; i++)
                #pragma unroll
                for (int j = 0; j < 8; j++) acc[i][j] += xv[i] * wv[j];
        }
        __syncthreads();
    }

    float asv[8], adv[8];
    #pragma unroll
    for (int j = 0; j < 8; j++) { asv[j] = a1s[cg * 8 + j]; adv[j] = a1d[cg * 8 + j]; }

    #pragma unroll
    for (int i = 0; i < 8; i++) {
        int gn = base + ng * 8 + i;
        if (gn < N_NODESC) {
            *(float4*)&g_h1[gn * D1C + cg * 8]     = make_float4(acc[i][0], acc[i][1], acc[i][2], acc[i][3]);
            *(float4*)&g_h1[gn * D1C + cg * 8 + 4] = make_float4(acc[i][4], acc[i][5], acc[i][6], acc[i][7]);
            float es = 0.f, ev = 0.f;
            #pragma unroll
            for (int j = 0; j < 8; j++) { es += acc[i][j] * asv[j]; ev += acc[i][j] * adv[j]; }
            g_e1s[gn * H1C + cg] = es;
            g_e1d[gn * H1C + cg] = ev;
        }
    }
}

// -------- layer1 gather: warp per dst, fused softmax-norm + ELU ---------
// Coalesced csr chunk loads + shfl; unroll x2 with independent chains.
__global__ void k_agg1() {
    int d    = (blockIdx.x * blockDim.x + threadIdx.x) >> 5;
    int lane = threadIdx.x & 31;
    if (d >= N_NODESC) return;
    const int h8 = lane & 7;
    const int la = lane >> 3, lb = 4 + (lane >> 3);
    float ed = g_e1d[d * H1C + h8];

    // self loop
    float p = __expf(lrelu(g_e1s[d * H1C + h8] + ed));
    float psum = p;
    float pa = __shfl_sync(FULLM, p, la);
    float pb = __shfl_sync(FULLM, p, lb);
    float acc0 = pa * g_h1[d * D1C + lane];
    float acc1 = pb * g_h1[d * D1C + 32 + lane];

    const int beg = g_off[d], n = g_deg[d];
    for (int j0 = 0; j0 < n; j0 += 32) {
        int idx = j0 + lane;
        int myS = (idx < n) ? g_csr[beg + idx] : 0;
        int lim = min(32, n - j0);
        int j = 0;
        for (; j + 1 < lim; j += 2) {
            int s0 = __shfl_sync(FULLM, myS, j);
            int s1 = __shfl_sync(FULLM, myS, j + 1);
            float es0 = g_e1s[s0 * H1C + h8];
            float es1 = g_e1s[s1 * H1C + h8];
            float p0 = __expf(lrelu(es0 + ed));
            float p1 = __expf(lrelu(es1 + ed));
            psum += p0 + p1;
            float pa0 = __shfl_sync(FULLM, p0, la);
            float pb0 = __shfl_sync(FULLM, p0, lb);
            float pa1 = __shfl_sync(FULLM, p1, la);
            float pb1 = __shfl_sync(FULLM, p1, lb);
            float h00 = g_h1[s0 * D1C + lane];
            float h01 = g_h1[s0 * D1C + 32 + lane];
            float h10 = g_h1[s1 * D1C + lane];
            float h11 = g_h1[s1 * D1C + 32 + lane];
            acc0 += pa0 * h00 + pa1 * h10;
            acc1 += pb0 * h01 + pb1 * h11;
        }
        if (j < lim) {
            int s0 = __shfl_sync(FULLM, myS, j);
            float p0 = __expf(lrelu(g_e1s[s0 * H1C + h8] + ed));
            psum += p0;
            float pa0 = __shfl_sync(FULLM, p0, la);
            float pb0 = __shfl_sync(FULLM, p0, lb);
            acc0 += pa0 * g_h1[s0 * D1C + lane];
            acc1 += pb0 * g_h1[s0 * D1C + 32 + lane];
        }
    }
    float sa = __shfl_sync(FULLM, psum, la);
    float sb = __shfl_sync(FULLM, psum, lb);
    float v0 = acc0 / sa, v1 = acc1 / sb;
    g_x2[d * D1C + lane]      = v0 > 0.f ? v0 : (__expf(v0) - 1.f);
    g_x2[d * D1C + 32 + lane] = v1 > 0.f ? v1 : (__expf(v1) - 1.f);
}

// -------- GEMM2 + fused e2s/e2d: h2 = x2 @ W2 (100000x64 @ 64x40) -------
__global__ __launch_bounds__(320) void k_gemm2(const float* __restrict__ W2,
                                               const float* __restrict__ a2s,
                                               const float* __restrict__ a2d) {
    __shared__ float xs[8][D1C];
    __shared__ float ws[D1C][NCC];
    __shared__ float rs[8][NCC];
    __shared__ float rd[8][NCC];
    const int t = threadIdx.x;
    const int base = blockIdx.x * 8;
    for (int i = t; i < D1C * NCC; i += 320) ws[i / NCC][i % NCC] = W2[i];
    for (int i = t; i < 8 * D1C; i += 320) {
        int n = i >> 6, j = i & 63;
        xs[n][j] = g_x2[(base + n) * D1C + j];
    }
    __syncthreads();
    const int n = t / NCC, c = t % NCC;
    float acc = 0.f;
    #pragma unroll 8
    for (int k = 0; k < D1C; k++) acc += xs[n][k] * ws[k][c];
    g_h2[(base + n) * NCC + c] = acc;
    rs[n][c] = acc * a2s[c];
    rd[n][c] = acc * a2d[c];
    __syncthreads();
    if (t < 8) {
        float sv = 0.f, dv = 0.f;
        #pragma unroll 8
        for (int c2 = 0; c2 < NCC; c2++) { sv += rs[t][c2]; dv += rd[t][c2]; }
        g_e2s[base + t] = sv;
        g_e2d[base + t] = dv;
    }
}

// -------- layer2 gather + log_softmax, warp per dst ---------------------
__global__ void k_agg2(float* __restrict__ out) {
    int d    = (blockIdx.x * blockDim.x + threadIdx.x) >> 5;
    int lane = threadIdx.x & 31;
    if (d >= N_NODESC) return;
    float ed = g_e2d[d];

    float p = __expf(lrelu(g_e2s[d] + ed));     // self loop
    float psum = p;
    float acc0 = p * g_h2[d * NCC + lane];
    float acc1 = (lane < 8) ? p * g_h2[d * NCC + 32 + lane] : 0.f;

    const int beg = g_off[d], n = g_deg[d];
    for (int j0 = 0; j0 < n; j0 += 32) {
        int idx = j0 + lane;
        int myS = (idx < n) ? g_csr[beg + idx] : 0;
        int lim = min(32, n - j0);
        int j = 0;
        for (; j + 1 < lim; j += 2) {
            int s0 = __shfl_sync(FULLM, myS, j);
            int s1 = __shfl_sync(FULLM, myS, j + 1);
            float p0 = __expf(lrelu(g_e2s[s0] + ed));
            float p1 = __expf(lrelu(g_e2s[s1] + ed));
            psum += p0 + p1;
            float h00 = g_h2[s0 * NCC + lane];
            float h10 = g_h2[s1 * NCC + lane];
            acc0 += p0 * h00 + p1 * h10;
            if (lane < 8) {
                float h01 = g_h2[s0 * NCC + 32 + lane];
                float h11 = g_h2[s1 * NCC + 32 + lane];
                acc1 += p0 * h01 + p1 * h11;
            }
        }
        if (j < lim) {
            int s0 = __shfl_sync(FULLM, myS, j);
            float p0 = __expf(lrelu(g_e2s[s0] + ed));
            psum += p0;
            acc0 += p0 * g_h2[s0 * NCC + lane];
            if (lane < 8) acc1 += p0 * g_h2[s0 * NCC + 32 + lane];
        }
    }
    float inv = 1.f / psum;
    float l1 = acc0 * inv;
    float l2 = (lane < 8) ? acc1 * inv : -1e30f;
    float m = fmaxf(l1, l2);
    #pragma unroll
    for (int o = 16; o; o >>= 1) m = fmaxf(m, __shfl_xor_sync(FULLM, m, o));
    float se = __expf(l1 - m) + ((lane < 8) ? __expf(l2 - m) : 0.f);
    #pragma unroll
    for (int o = 16; o; o >>= 1) se += __shfl_xor_sync(FULLM, se, o);
    float lse = m + logf(se);
    out[d * NCC + lane] = l1 - lse;
    if (lane < 8) out[d * NCC + 32 + lane] = l2 - lse;
}

// ------------------------------------------------------------------------
extern "C" void kernel_launch(void* const* d_in, const int* in_sizes, int n_in,
                              void* d_out, int out_size) {
    const float* x   = (const float*)d_in[0];
    const void*  adj = d_in[1];
    const float* W1  = (const float*)d_in[2];
    const float* a1s = (const float*)d_in[3];
    const float* a1d = (const float*)d_in[4];
    const float* W2  = (const float*)d_in[5];
    const float* a2s = (const float*)d_in[6];
    const float* a2d = (const float*)d_in[7];
    float* out = (float*)d_out;

    const int eg = (N_EDGESC + 255) / 256;      // 12500
    const int ng = (N_NODESC + 255) / 256;      // 391
    const int wg = N_NODESC / 8;                // 12500 (warp per node)

    k_detect <<<1, 32>>>((const long long*)adj);            // 0
    k_init   <<<ng, 256>>>();                               // 1
    k_hist   <<<eg, 256>>>(adj);                            // 2
    k_gemm1  <<<(N_NODESC + 127) / 128, 128>>>(x, W1, a1s, a1d);  // 3 <- profiled
    k_scan1  <<<NB_SCAN, 512>>>();                          // 4
    k_scan2  <<<1, 256>>>();                                // 5
    k_scan3  <<<ng, 256>>>();                               // 6
    k_fill   <<<eg, 256>>>(adj);                            // 7
    k_agg1   <<<wg, 256>>>();                               // 8
    k_gemm2  <<<(N_NODESC + 7) / 8, 320>>>(W2, a2s, a2d);   // 9
    k_agg2   <<<wg, 256>>>(out);                            // 10
}